// round 4
// baseline (speedup 1.0000x reference)
#include <cuda_runtime.h>
#include <cfloat>

#define NPTS 8192
#define BB 2
#define RR 2048
#define KK 16
#define CINC 64
#define CLC 16
#define COUTC 128
#define KSQ 256
#define NGRP (BB*RR)      /* 4096 */
#define FEATC 80          /* CLC + CINC */
#define FLEN 1280         /* KK*FEATC */

// ---------------- scratch (device globals; no allocation allowed) ----------------
__device__ float g_pf[NGRP*48];
__device__ float g_feat[NGRP*FLEN];
__device__ float g_h1[NGRP*KSQ];
__device__ float g_h2[NGRP*KSQ];
__device__ float g_T[NGRP*KSQ];
__device__ float g_Tf[NGRP*FLEN];
__device__ float g_cw[COUTC*FLEN];
__device__ int   g_nb[NGRP*KK];
__device__ float g_sq[BB*NPTS];

// ---------------- sq = sum(points*points, -1), canonical XLA rounding (no FMA) ----------------
__global__ void sq_kernel(const float* __restrict__ points) {
    const int i = blockIdx.x*256 + threadIdx.x;
    if (i < BB*NPTS) {
        const float x = points[i*3+0], y = points[i*3+1], z = points[i*3+2];
        g_sq[i] = __fadd_rn(__fadd_rn(__fmul_rn(x,x), __fmul_rn(y,y)), __fmul_rn(z,z));
    }
}

// ---------------- KNN: top-17 (ascending d2, stable index tie-break), drop self ----------------
// d2 matches reference bit pattern: d2 = (sq_q + sq_j) - 2*dot, with dot accumulated
// via sequential FMA over the 3 coords (gemm-style), sq precomputed without FMA.
__global__ void knn_kernel(const float* __restrict__ points, const int* __restrict__ rep_idx) {
    const int b = blockIdx.y;
    const float* __restrict__ P  = points + (size_t)b * NPTS * 3;
    const float* __restrict__ SQ = g_sq + (size_t)b * NPTS;
    __shared__ float swv[8];
    __shared__ int   swi[8];
    __shared__ int   s_gi;
    __shared__ int   s_nb[17];
    const int tid  = threadIdx.x;          // 256 threads
    const int lane = tid & 31;
    const int warp = tid >> 5;

    for (int r = blockIdx.x; r < RR; r += gridDim.x) {
        const int rp = rep_idx[r];
        const float qx = P[rp*3+0], qy = P[rp*3+1], qz = P[rp*3+2];
        const float sqq = SQ[rp];

        float dloc[32];                    // thread-private candidate distances
        float bv = FLT_MAX; int bi = 0x7FFFFFFF;
        #pragma unroll 4
        for (int i = 0; i < 32; i++) {
            const int j = tid + (i << 8);
            const float px = P[j*3+0], py = P[j*3+1], pz = P[j*3+2];
            // dot: sequential FMA in coordinate order (matches gemm K-accumulation)
            float dt = __fmul_rn(px, qx);
            dt = __fmaf_rn(py, qy, dt);
            dt = __fmaf_rn(pz, qz, dt);
            // d2 = (sq_q + sq_j) - 2*dot  (2*dot exact; subtract rounding unambiguous)
            const float d2 = __fsub_rn(__fadd_rn(sqq, SQ[j]), __fmul_rn(2.0f, dt));
            dloc[i] = d2;
            if (d2 < bv) { bv = d2; bi = j; }         // strict <: smallest j wins per thread
        }

        for (int round = 0; round < 17; round++) {
            float v = bv; int ii = bi;
            #pragma unroll
            for (int off = 16; off > 0; off >>= 1) {
                const float ov = __shfl_down_sync(0xFFFFFFFFu, v, off);
                const int   oi = __shfl_down_sync(0xFFFFFFFFu, ii, off);
                if (ov < v || (ov == v && oi < ii)) { v = ov; ii = oi; }
            }
            if (lane == 0) { swv[warp] = v; swi[warp] = ii; }
            __syncthreads();
            if (warp == 0) {
                v  = (lane < 8) ? swv[lane] : FLT_MAX;
                ii = (lane < 8) ? swi[lane] : 0x7FFFFFFF;
                #pragma unroll
                for (int off = 4; off > 0; off >>= 1) {
                    const float ov = __shfl_down_sync(0xFFFFFFFFu, v, off);
                    const int   oi = __shfl_down_sync(0xFFFFFFFFu, ii, off);
                    if (ov < v || (ov == v && oi < ii)) { v = ov; ii = oi; }
                }
                if (lane == 0) { s_gi = ii; s_nb[round] = ii; }
            }
            __syncthreads();
            const int wi = s_gi;
            if (bi == wi) {                      // only the winner rescans its 32
                dloc[(wi - tid) >> 8] = FLT_MAX;
                bv = FLT_MAX; bi = 0x7FFFFFFF;
                #pragma unroll
                for (int i = 0; i < 32; i++) {
                    if (dloc[i] < bv) { bv = dloc[i]; bi = tid + (i << 8); }
                }
            }
        }
        __syncthreads();
        if (tid < KK) g_nb[((size_t)(b*RR + r))*KK + tid] = s_nb[tid + 1];  // drop self
        __syncthreads();
    }
}

// ---------------- gather + p/pf + lifted + feat concat + rep_pos ----------------
__global__ void assemble_kernel(const float* __restrict__ points, const float* __restrict__ features,
                                const float* __restrict__ lift_w, const float* __restrict__ lift_b,
                                const float* __restrict__ bn_g,   const float* __restrict__ bn_b,
                                const int* __restrict__ rep_idx,  float* __restrict__ rep_pos_out) {
    const int g = blockIdx.x;                     // 0..4095
    const int b = g / RR, r = g % RR;
    const int tid = threadIdx.x;                  // 128
    __shared__ float p[KK][3];
    __shared__ int   nj[KK];
    __shared__ float q[3];

    if (tid < KK) nj[tid] = g_nb[(size_t)g*KK + tid];
    if (tid >= 32 && tid < 35) {
        const int rp = rep_idx[r];
        q[tid-32] = points[((size_t)b*NPTS + rp)*3 + (tid-32)];
    }
    __syncthreads();

    if (tid < 48) {
        const int k = tid / 3, d = tid % 3;
        const float val = points[((size_t)b*NPTS + nj[k])*3 + d] - q[d];
        p[k][d] = val;
        g_pf[(size_t)g*48 + tid] = val;           // pf layout: k major, d minor
    }
    if (tid >= 64 && tid < 67) rep_pos_out[(size_t)g*3 + (tid-64)] = q[tid-64];
    __syncthreads();

    // lifted = relu(bn(p @ lift_w.T + lift_b))
    for (int idx = tid; idx < KK*CLC; idx += 128) {
        const int k = idx >> 4, l = idx & 15;
        float v = p[k][0]*lift_w[l*3+0] + p[k][1]*lift_w[l*3+1] + p[k][2]*lift_w[l*3+2];
        v = (v + lift_b[l]) * bn_g[l] + bn_b[l];
        g_feat[(size_t)g*FLEN + k*FEATC + l] = fmaxf(v, 0.0f);
    }
    // nbr features
    for (int idx = tid; idx < KK*CINC; idx += 128) {
        const int k = idx >> 6, c = idx & 63;
        g_feat[(size_t)g*FLEN + k*FEATC + CLC + c] = features[((size_t)b*NPTS + nj[k])*CINC + c];
    }
}

// ---------------- tiled GEMM: C[M,N] = A[M,Kd] * W[N,Kd]^T, fused bias/bn/relu ----------------
template<bool RELU, bool DOBN>
__global__ void gemm_bn_kernel(const float* __restrict__ A, const float* __restrict__ W,
                               const float* __restrict__ bias, const float* __restrict__ bng,
                               const float* __restrict__ bnb, float* __restrict__ C,
                               int M, int N, int Kd) {
    const int BM = 64, BN_ = 64, BK = 16;
    __shared__ __align__(16) float As[BK][BM+4];
    __shared__ __align__(16) float Bs[BK][BN_+4];
    const int bm = blockIdx.x * BM;
    const int bn = blockIdx.y * BN_;
    const int tid = threadIdx.x;                  // 256
    const int tx = tid & 15, ty = tid >> 4;
    const int lm = tid >> 2;                      // 0..63
    const int lk = (tid & 3) << 2;                // 0,4,8,12
    float acc[4][4] = {};

    for (int k0 = 0; k0 < Kd; k0 += BK) {
        const float4 av = *(const float4*)(A + (size_t)(bm + lm)*Kd + k0 + lk);
        const float4 bv = *(const float4*)(W + (size_t)(bn + lm)*Kd + k0 + lk);
        As[lk+0][lm] = av.x; As[lk+1][lm] = av.y; As[lk+2][lm] = av.z; As[lk+3][lm] = av.w;
        Bs[lk+0][lm] = bv.x; Bs[lk+1][lm] = bv.y; Bs[lk+2][lm] = bv.z; Bs[lk+3][lm] = bv.w;
        __syncthreads();
        #pragma unroll
        for (int kk = 0; kk < BK; kk++) {
            const float4 a = *(const float4*)(&As[kk][ty*4]);
            const float4 bq = *(const float4*)(&Bs[kk][tx*4]);
            const float ar[4] = {a.x, a.y, a.z, a.w};
            const float br[4] = {bq.x, bq.y, bq.z, bq.w};
            #pragma unroll
            for (int i = 0; i < 4; i++)
                #pragma unroll
                for (int j = 0; j < 4; j++)
                    acc[i][j] = fmaf(ar[i], br[j], acc[i][j]);
        }
        __syncthreads();
    }
    #pragma unroll
    for (int j = 0; j < 4; j++) {
        const int n = bn + tx*4 + j;
        const float bia = bias[n];
        const float gg = DOBN ? bng[n] : 0.0f;
        const float be = DOBN ? bnb[n] : 0.0f;
        #pragma unroll
        for (int i = 0; i < 4; i++) {
            float v = acc[i][j] + bia;
            if (DOBN) v = v*gg + be;
            if (RELU) v = fmaxf(v, 0.0f);
            C[(size_t)(bm + ty*4 + i)*N + n] = v;
        }
    }
}

// ---------------- per-group Tf = T[16,16] @ feat[16,80] ----------------
__global__ void tf_kernel() {
    const int g = blockIdx.x;
    const int tid = threadIdx.x;                  // 128
    __shared__ float Ts[KSQ];
    __shared__ float fs[FLEN];
    for (int i = tid; i < KSQ;  i += 128) Ts[i] = g_T[(size_t)g*KSQ + i];
    for (int i = tid; i < FLEN; i += 128) fs[i] = g_feat[(size_t)g*FLEN + i];
    __syncthreads();
    for (int idx = tid; idx < FLEN; idx += 128) {
        const int k = idx / FEATC, c = idx % FEATC;
        float s = 0.0f;
        #pragma unroll
        for (int j = 0; j < KK; j++) s = fmaf(Ts[k*KK + j], fs[j*FEATC + c], s);
        g_Tf[(size_t)g*FLEN + idx] = s;
    }
}

// ---------------- conv_w [O,C,K] -> g_cw [O, k*80+c] ----------------
__global__ void prep_cw_kernel(const float* __restrict__ conv_w) {
    const int i = blockIdx.x*256 + threadIdx.x;
    if (i < COUTC*FLEN) {
        const int o = i / FLEN, kc = i % FLEN;
        const int k = kc / FEATC, c = kc % FEATC;
        g_cw[i] = conv_w[(o*FEATC + c)*KK + k];
    }
}

// ---------------- launch ----------------
extern "C" void kernel_launch(void* const* d_in, const int* in_sizes, int n_in,
                              void* d_out, int out_size) {
    const float* points   = (const float*)d_in[0];
    const float* features = (const float*)d_in[1];
    const float* lift_w   = (const float*)d_in[2];
    const float* lift_b   = (const float*)d_in[3];
    const float* blg      = (const float*)d_in[4];
    const float* blb      = (const float*)d_in[5];
    const float* t1_w     = (const float*)d_in[6];
    const float* t1_b     = (const float*)d_in[7];
    const float* b1g      = (const float*)d_in[8];
    const float* b1b      = (const float*)d_in[9];
    const float* t2_w     = (const float*)d_in[10];
    const float* t2_b     = (const float*)d_in[11];
    const float* b2g      = (const float*)d_in[12];
    const float* b2b      = (const float*)d_in[13];
    const float* t3_w     = (const float*)d_in[14];
    const float* t3_b     = (const float*)d_in[15];
    const float* b3g      = (const float*)d_in[16];
    const float* b3b      = (const float*)d_in[17];
    const float* conv_w   = (const float*)d_in[18];
    const float* conv_b   = (const float*)d_in[19];
    const int*   rep_idx  = (const int*)d_in[20];
    float* out = (float*)d_out;

    float *pf, *h1, *h2, *T, *Tf, *cw;
    cudaGetSymbolAddress((void**)&pf, g_pf);
    cudaGetSymbolAddress((void**)&h1, g_h1);
    cudaGetSymbolAddress((void**)&h2, g_h2);
    cudaGetSymbolAddress((void**)&T,  g_T);
    cudaGetSymbolAddress((void**)&Tf, g_Tf);
    cudaGetSymbolAddress((void**)&cw, g_cw);

    prep_cw_kernel<<<(COUTC*FLEN + 255)/256, 256>>>(conv_w);
    sq_kernel<<<(BB*NPTS + 255)/256, 256>>>(points);
    knn_kernel<<<dim3(128, BB), 256>>>(points, rep_idx);
    assemble_kernel<<<NGRP, 128>>>(points, features, lift_w, lift_b, blg, blb, rep_idx, out);
    gemm_bn_kernel<true,  true ><<<dim3(NGRP/64, KSQ/64),   256>>>(pf, t1_w, t1_b, b1g, b1b, h1, NGRP, KSQ, 48);
    gemm_bn_kernel<true,  true ><<<dim3(NGRP/64, KSQ/64),   256>>>(h1, t2_w, t2_b, b2g, b2b, h2, NGRP, KSQ, KSQ);
    gemm_bn_kernel<false, true ><<<dim3(NGRP/64, KSQ/64),   256>>>(h2, t3_w, t3_b, b3g, b3b, T,  NGRP, KSQ, KSQ);
    tf_kernel<<<NGRP, 128>>>();
    gemm_bn_kernel<false, false><<<dim3(NGRP/64, COUTC/64), 256>>>(Tf, cw, conv_b, nullptr, nullptr,
                                                                   out + (size_t)NGRP*3, NGRP, COUTC, FLEN);
}

// round 9
// speedup vs baseline: 1.5583x; 1.5583x over previous
#include <cuda_runtime.h>
#include <cstdint>
#include <cfloat>

#define NPTS 8192
#define BB 2
#define RR 2048
#define KK 16
#define CINC 64
#define CLC 16
#define COUTC 128
#define KSQ 256
#define NGRP (BB*RR)      /* 4096 */
#define FEATC 80          /* CLC + CINC */
#define FLEN 1280         /* KK*FEATC */

// ---------------- scratch (device globals; no allocation allowed) ----------------
__device__ float g_pf[NGRP*48];
__device__ float g_feat[NGRP*FLEN];
__device__ float g_h1[NGRP*KSQ];
__device__ float g_h2[NGRP*KSQ];
__device__ float g_T[NGRP*KSQ];
__device__ float g_Tf[NGRP*FLEN];
__device__ float g_cw[COUTC*FLEN];
__device__ int   g_nb[NGRP*KK];
__device__ float g_sq[BB*NPTS];

// ---------------- sq = sum(points*points, -1), canonical XLA rounding (no FMA) ----------------
__global__ void sq_kernel(const float* __restrict__ points) {
    const int i = blockIdx.x*256 + threadIdx.x;
    if (i < BB*NPTS) {
        const float x = points[i*3+0], y = points[i*3+1], z = points[i*3+2];
        g_sq[i] = __fadd_rn(__fadd_rn(__fmul_rn(x,x), __fmul_rn(y,y)), __fmul_rn(z,z));
    }
}

// ---------------- KNN: top-17 (ascending d2, stable index tie-break), drop self ----------------
// d2 matches reference bit pattern: d2 = (sq_q + sq_j) - 2*dot, with dot accumulated
// via sequential FMA over the 3 coords (gemm-style), sq precomputed without FMA.
__global__ void knn_kernel(const float* __restrict__ points, const int* __restrict__ rep_idx) {
    const int b = blockIdx.y;
    const float* __restrict__ P  = points + (size_t)b * NPTS * 3;
    const float* __restrict__ SQ = g_sq + (size_t)b * NPTS;
    __shared__ float swv[8];
    __shared__ int   swi[8];
    __shared__ int   s_gi;
    __shared__ int   s_nb[17];
    const int tid  = threadIdx.x;          // 256 threads
    const int lane = tid & 31;
    const int warp = tid >> 5;

    for (int r = blockIdx.x; r < RR; r += gridDim.x) {
        const int rp = rep_idx[r];
        const float qx = P[rp*3+0], qy = P[rp*3+1], qz = P[rp*3+2];
        const float sqq = SQ[rp];

        float dloc[32];                    // thread-private candidate distances
        float bv = FLT_MAX; int bi = 0x7FFFFFFF;
        #pragma unroll 4
        for (int i = 0; i < 32; i++) {
            const int j = tid + (i << 8);
            const float px = P[j*3+0], py = P[j*3+1], pz = P[j*3+2];
            float dt = __fmul_rn(px, qx);
            dt = __fmaf_rn(py, qy, dt);
            dt = __fmaf_rn(pz, qz, dt);
            const float d2 = __fsub_rn(__fadd_rn(sqq, SQ[j]), __fmul_rn(2.0f, dt));
            dloc[i] = d2;
            if (d2 < bv) { bv = d2; bi = j; }
        }

        for (int round = 0; round < 17; round++) {
            float v = bv; int ii = bi;
            #pragma unroll
            for (int off = 16; off > 0; off >>= 1) {
                const float ov = __shfl_down_sync(0xFFFFFFFFu, v, off);
                const int   oi = __shfl_down_sync(0xFFFFFFFFu, ii, off);
                if (ov < v || (ov == v && oi < ii)) { v = ov; ii = oi; }
            }
            if (lane == 0) { swv[warp] = v; swi[warp] = ii; }
            __syncthreads();
            if (warp == 0) {
                v  = (lane < 8) ? swv[lane] : FLT_MAX;
                ii = (lane < 8) ? swi[lane] : 0x7FFFFFFF;
                #pragma unroll
                for (int off = 4; off > 0; off >>= 1) {
                    const float ov = __shfl_down_sync(0xFFFFFFFFu, v, off);
                    const int   oi = __shfl_down_sync(0xFFFFFFFFu, ii, off);
                    if (ov < v || (ov == v && oi < ii)) { v = ov; ii = oi; }
                }
                if (lane == 0) { s_gi = ii; s_nb[round] = ii; }
            }
            __syncthreads();
            const int wi = s_gi;
            if (bi == wi) {                      // only the winner rescans its 32
                dloc[(wi - tid) >> 8] = FLT_MAX;
                bv = FLT_MAX; bi = 0x7FFFFFFF;
                #pragma unroll
                for (int i = 0; i < 32; i++) {
                    if (dloc[i] < bv) { bv = dloc[i]; bi = tid + (i << 8); }
                }
            }
        }
        __syncthreads();
        if (tid < KK) g_nb[((size_t)(b*RR + r))*KK + tid] = s_nb[tid + 1];  // drop self
        __syncthreads();
    }
}

// ---------------- gather + p/pf + lifted + feat concat + rep_pos ----------------
__global__ void assemble_kernel(const float* __restrict__ points, const float* __restrict__ features,
                                const float* __restrict__ lift_w, const float* __restrict__ lift_b,
                                const float* __restrict__ bn_g,   const float* __restrict__ bn_b,
                                const int* __restrict__ rep_idx,  float* __restrict__ rep_pos_out) {
    const int g = blockIdx.x;                     // 0..4095
    const int b = g / RR, r = g % RR;
    const int tid = threadIdx.x;                  // 128
    __shared__ float p[KK][3];
    __shared__ int   nj[KK];
    __shared__ float q[3];

    if (tid < KK) nj[tid] = g_nb[(size_t)g*KK + tid];
    if (tid >= 32 && tid < 35) {
        const int rp = rep_idx[r];
        q[tid-32] = points[((size_t)b*NPTS + rp)*3 + (tid-32)];
    }
    __syncthreads();

    if (tid < 48) {
        const int k = tid / 3, d = tid % 3;
        const float val = points[((size_t)b*NPTS + nj[k])*3 + d] - q[d];
        p[k][d] = val;
        g_pf[(size_t)g*48 + tid] = val;
    }
    if (tid >= 64 && tid < 67) rep_pos_out[(size_t)g*3 + (tid-64)] = q[tid-64];
    __syncthreads();

    for (int idx = tid; idx < KK*CLC; idx += 128) {
        const int k = idx >> 4, l = idx & 15;
        float v = p[k][0]*lift_w[l*3+0] + p[k][1]*lift_w[l*3+1] + p[k][2]*lift_w[l*3+2];
        v = (v + lift_b[l]) * bn_g[l] + bn_b[l];
        g_feat[(size_t)g*FLEN + k*FEATC + l] = fmaxf(v, 0.0f);
    }
    for (int idx = tid; idx < KK*CINC; idx += 128) {
        const int k = idx >> 6, c = idx & 63;
        g_feat[(size_t)g*FLEN + k*FEATC + CLC + c] = features[((size_t)b*NPTS + nj[k])*CINC + c];
    }
}

// ---------------- tf32x3 helpers ----------------
__device__ __forceinline__ void f2tf32x2(float x, uint32_t& hi, uint32_t& lo) {
    asm("cvt.rna.tf32.f32 %0, %1;" : "=r"(hi) : "f"(x));
    const float l = __fsub_rn(x, __uint_as_float(hi));
    asm("cvt.rna.tf32.f32 %0, %1;" : "=r"(lo) : "f"(l));
}
__device__ __forceinline__ void mma_tf32(float* c, const uint32_t* a, const uint32_t* b) {
    asm volatile("mma.sync.aligned.m16n8k8.row.col.f32.tf32.tf32.f32 "
        "{%0,%1,%2,%3}, {%4,%5,%6,%7}, {%8,%9}, {%0,%1,%2,%3};"
        : "+f"(c[0]), "+f"(c[1]), "+f"(c[2]), "+f"(c[3])
        : "r"(a[0]), "r"(a[1]), "r"(a[2]), "r"(a[3]), "r"(b[0]), "r"(b[1]));
}

// ---------------- tensor-core GEMM (tf32x3): C[M,N] = A[M,Kd]*W[N,Kd]^T, fused epilogue -----
// CTA tile 64x64, 128 threads = 4 warps in 2x2, warp tile 32x32.
// Smem stride 36 => fragment LDS addr = 4*m + k (mod 32): conflict-free.
template<int BK, bool RELU, bool DOBN>
__global__ void gemm_mma_kernel(const float* __restrict__ A, const float* __restrict__ W,
                                const float* __restrict__ bias, const float* __restrict__ bng,
                                const float* __restrict__ bnb, float* __restrict__ C,
                                int M, int N, int Kd) {
    __shared__ float As[64*36];
    __shared__ float Bs[64*36];
    const int bm = blockIdx.x * 64;
    const int bn = blockIdx.y * 64;
    const int tid = threadIdx.x;                  // 128
    const int lane = tid & 31;
    const int wid  = tid >> 5;
    const int wm = wid & 1, wn = wid >> 1;        // 2x2 warps
    const int gq = lane >> 2;                     // groupID 0..7
    const int tg = lane & 3;                      // thread-in-group 0..3

    float acc[2][4][4];
    #pragma unroll
    for (int a = 0; a < 2; a++)
        #pragma unroll
        for (int b = 0; b < 4; b++)
            #pragma unroll
            for (int c = 0; c < 4; c++) acc[a][b][c] = 0.0f;

    const int NF4 = BK / 8;                       // float4 loads per thread per tile
    for (int k0 = 0; k0 < Kd; k0 += BK) {
        #pragma unroll
        for (int i = 0; i < NF4; i++) {
            const int idx = tid + 128*i;          // 0 .. 64*BK/4-1
            const int row = idx / (BK/4);
            const int c4  = idx % (BK/4);
            const float4 av = *(const float4*)(A + (size_t)(bm + row)*Kd + k0 + c4*4);
            *(float4*)&As[row*36 + c4*4] = av;
            const float4 bv = *(const float4*)(W + (size_t)(bn + row)*Kd + k0 + c4*4);
            *(float4*)&Bs[row*36 + c4*4] = bv;
        }
        __syncthreads();

        #pragma unroll
        for (int ks = 0; ks < BK; ks += 8) {
            uint32_t ahi[2][4], alo[2][4], bhi[4][2], blo[4][2];
            #pragma unroll
            for (int mt = 0; mt < 2; mt++) {
                const int m0 = wm*32 + mt*16 + gq;
                f2tf32x2(As[(m0  )*36 + ks + tg    ], ahi[mt][0], alo[mt][0]);
                f2tf32x2(As[(m0+8)*36 + ks + tg    ], ahi[mt][1], alo[mt][1]);
                f2tf32x2(As[(m0  )*36 + ks + tg + 4], ahi[mt][2], alo[mt][2]);
                f2tf32x2(As[(m0+8)*36 + ks + tg + 4], ahi[mt][3], alo[mt][3]);
            }
            #pragma unroll
            for (int nt = 0; nt < 4; nt++) {
                const int n0 = wn*32 + nt*8 + gq;
                f2tf32x2(Bs[n0*36 + ks + tg    ], bhi[nt][0], blo[nt][0]);
                f2tf32x2(Bs[n0*36 + ks + tg + 4], bhi[nt][1], blo[nt][1]);
            }
            #pragma unroll
            for (int mt = 0; mt < 2; mt++)
                #pragma unroll
                for (int nt = 0; nt < 4; nt++) {
                    mma_tf32(acc[mt][nt], alo[mt], bhi[nt]);
                    mma_tf32(acc[mt][nt], ahi[mt], blo[nt]);
                    mma_tf32(acc[mt][nt], ahi[mt], bhi[nt]);
                }
        }
        __syncthreads();
    }

    // epilogue
    #pragma unroll
    for (int mt = 0; mt < 2; mt++) {
        const int row0 = bm + wm*32 + mt*16 + gq;
        #pragma unroll
        for (int nt = 0; nt < 4; nt++) {
            const int col0 = bn + wn*32 + nt*8 + 2*tg;
            float vv[4];
            #pragma unroll
            for (int j = 0; j < 2; j++) {
                const int n = col0 + j;
                const float bia = bias[n];
                float v0 = acc[mt][nt][j]   + bia;
                float v1 = acc[mt][nt][j+2] + bia;
                if (DOBN) {
                    const float gg = bng[n], be = bnb[n];
                    v0 = v0*gg + be; v1 = v1*gg + be;
                }
                if (RELU) { v0 = fmaxf(v0, 0.0f); v1 = fmaxf(v1, 0.0f); }
                vv[j] = v0; vv[j+2] = v1;
            }
            *(float2*)&C[(size_t)row0*N + col0]     = make_float2(vv[0], vv[1]);
            *(float2*)&C[(size_t)(row0+8)*N + col0] = make_float2(vv[2], vv[3]);
        }
    }
}

// ---------------- per-group Tf = T[16,16] @ feat[16,80] ----------------
__global__ void tf_kernel() {
    const int g = blockIdx.x;
    const int tid = threadIdx.x;                  // 128
    __shared__ float Ts[KSQ];
    __shared__ float fs[FLEN];
    for (int i = tid; i < KSQ;  i += 128) Ts[i] = g_T[(size_t)g*KSQ + i];
    for (int i = tid; i < FLEN; i += 128) fs[i] = g_feat[(size_t)g*FLEN + i];
    __syncthreads();
    for (int idx = tid; idx < FLEN; idx += 128) {
        const int k = idx / FEATC, c = idx % FEATC;
        float s = 0.0f;
        #pragma unroll
        for (int j = 0; j < KK; j++) s = fmaf(Ts[k*KK + j], fs[j*FEATC + c], s);
        g_Tf[(size_t)g*FLEN + idx] = s;
    }
}

// ---------------- conv_w [O,C,K] -> g_cw [O, k*80+c] ----------------
__global__ void prep_cw_kernel(const float* __restrict__ conv_w) {
    const int i = blockIdx.x*256 + threadIdx.x;
    if (i < COUTC*FLEN) {
        const int o = i / FLEN, kc = i % FLEN;
        const int k = kc / FEATC, c = kc % FEATC;
        g_cw[i] = conv_w[(o*FEATC + c)*KK + k];
    }
}

// ---------------- launch ----------------
extern "C" void kernel_launch(void* const* d_in, const int* in_sizes, int n_in,
                              void* d_out, int out_size) {
    const float* points   = (const float*)d_in[0];
    const float* features = (const float*)d_in[1];
    const float* lift_w   = (const float*)d_in[2];
    const float* lift_b   = (const float*)d_in[3];
    const float* blg      = (const float*)d_in[4];
    const float* blb      = (const float*)d_in[5];
    const float* t1_w     = (const float*)d_in[6];
    const float* t1_b     = (const float*)d_in[7];
    const float* b1g      = (const float*)d_in[8];
    const float* b1b      = (const float*)d_in[9];
    const float* t2_w     = (const float*)d_in[10];
    const float* t2_b     = (const float*)d_in[11];
    const float* b2g      = (const float*)d_in[12];
    const float* b2b      = (const float*)d_in[13];
    const float* t3_w     = (const float*)d_in[14];
    const float* t3_b     = (const float*)d_in[15];
    const float* b3g      = (const float*)d_in[16];
    const float* b3b      = (const float*)d_in[17];
    const float* conv_w   = (const float*)d_in[18];
    const float* conv_b   = (const float*)d_in[19];
    const int*   rep_idx  = (const int*)d_in[20];
    float* out = (float*)d_out;

    float *pf, *h1, *h2, *T, *Tf, *cw;
    cudaGetSymbolAddress((void**)&pf, g_pf);
    cudaGetSymbolAddress((void**)&h1, g_h1);
    cudaGetSymbolAddress((void**)&h2, g_h2);
    cudaGetSymbolAddress((void**)&T,  g_T);
    cudaGetSymbolAddress((void**)&Tf, g_Tf);
    cudaGetSymbolAddress((void**)&cw, g_cw);

    prep_cw_kernel<<<(COUTC*FLEN + 255)/256, 256>>>(conv_w);
    sq_kernel<<<(BB*NPTS + 255)/256, 256>>>(points);
    knn_kernel<<<dim3(256, BB), 256>>>(points, rep_idx);
    assemble_kernel<<<NGRP, 128>>>(points, features, lift_w, lift_b, blg, blb, rep_idx, out);
    gemm_mma_kernel<16, true,  true ><<<dim3(NGRP/64, KSQ/64),   128>>>(pf, t1_w, t1_b, b1g, b1b, h1, NGRP, KSQ, 48);
    gemm_mma_kernel<32, true,  true ><<<dim3(NGRP/64, KSQ/64),   128>>>(h1, t2_w, t2_b, b2g, b2b, h2, NGRP, KSQ, KSQ);
    gemm_mma_kernel<32, false, true ><<<dim3(NGRP/64, KSQ/64),   128>>>(h2, t3_w, t3_b, b3g, b3b, T,  NGRP, KSQ, KSQ);
    tf_kernel<<<NGRP, 128>>>();
    gemm_mma_kernel<32, false, false><<<dim3(NGRP/64, COUTC/64), 128>>>(Tf, cw, conv_b, nullptr, nullptr,
                                                                        out + (size_t)NGRP*3, NGRP, COUTC, FLEN);
}